// round 17
// baseline (speedup 1.0000x reference)
#include <cuda_runtime.h>
#include <cuda_fp16.h>
#include <cstdint>

#define BB 4
#define SS 1024
#define HH 8
#define DHD 64
#define DD 512
#define NR 11
#define EC 0.18033688f   // 0.125 * log2(e)

// fp16 projected Q/K/V in [B,H,S,DH], indexed by z (0=Q,1=K,2=V)
__device__ __half g_p16[3][BB*HH*SS*DHD];

// fp16 inputs x (q,k,v) and transposed weights Wt[n][k]
__device__ __half g_x16[3][BB*SS*DD];
__device__ __half g_wt16[3][DD*DD];

// nibble-packed rpr matrix (2 values per byte, low nibble = even col)
__device__ uint8_t g_rpr4[SS*SS/2];

// ===========================================================================
// PTX helpers (base sm_103)
// ===========================================================================
__device__ __forceinline__ void mma_f16(float* c, const uint32_t* a,
                                        const uint32_t* b) {
    asm volatile(
        "mma.sync.aligned.m16n8k16.row.col.f32.f16.f16.f32 "
        "{%0,%1,%2,%3}, {%4,%5,%6,%7}, {%8,%9}, {%0,%1,%2,%3};"
        : "+f"(c[0]), "+f"(c[1]), "+f"(c[2]), "+f"(c[3])
        : "r"(a[0]), "r"(a[1]), "r"(a[2]), "r"(a[3]), "r"(b[0]), "r"(b[1]));
}
__device__ __forceinline__ void ldmatrix_x4(uint32_t& r0, uint32_t& r1,
                                            uint32_t& r2, uint32_t& r3,
                                            uint32_t addr) {
    asm volatile(
        "ldmatrix.sync.aligned.m8n8.x4.shared.b16 {%0,%1,%2,%3}, [%4];"
        : "=r"(r0), "=r"(r1), "=r"(r2), "=r"(r3) : "r"(addr));
}
__device__ __forceinline__ void ldmatrix_x4_t(uint32_t& r0, uint32_t& r1,
                                              uint32_t& r2, uint32_t& r3,
                                              uint32_t addr) {
    asm volatile(
        "ldmatrix.sync.aligned.m8n8.x4.trans.shared.b16 {%0,%1,%2,%3}, [%4];"
        : "=r"(r0), "=r"(r1), "=r"(r2), "=r"(r3) : "r"(addr));
}
__device__ __forceinline__ uint32_t pack_h2(float lo, float hi) {
    __half2 h = __floats2half2_rn(lo, hi);
    return *(uint32_t*)&h;
}
__device__ __forceinline__ uint32_t smem_u32(const void* p) {
    uint32_t a;
    asm("{ .reg .u64 t; cvta.to.shared.u64 t, %1; cvt.u32.u64 %0, t; }"
        : "=r"(a) : "l"(p));
    return a;
}
#define CP16(dst, src) \
    asm volatile("cp.async.cg.shared.global [%0], [%1], 16;" \
                 :: "r"(dst), "l"(src) : "memory")
#define CP_COMMIT() asm volatile("cp.async.commit_group;" ::: "memory")
#define CP_WAIT1() asm volatile("cp.async.wait_group 1;" ::: "memory")
#define CP_WAIT0() asm volatile("cp.async.wait_group 0;" ::: "memory")

// ===========================================================================
// Prepass kernels
// ===========================================================================
__global__ __launch_bounds__(256) void convert_x(
    const float* __restrict__ q, const float* __restrict__ k,
    const float* __restrict__ v)
{
    int z = blockIdx.y;
    const float* src = (z == 0) ? q : (z == 1) ? k : v;
    size_t i = (size_t)blockIdx.x * 256 + threadIdx.x;   // 8-float group
    float4 x0 = ((const float4*)src)[2 * i];
    float4 x1 = ((const float4*)src)[2 * i + 1];
    uint4 o;
    o.x = pack_h2(x0.x, x0.y); o.y = pack_h2(x0.z, x0.w);
    o.z = pack_h2(x1.x, x1.y); o.w = pack_h2(x1.z, x1.w);
    ((uint4*)(g_x16[z]))[i] = o;
}

__global__ __launch_bounds__(256) void convert_w(
    const float* __restrict__ wq, const float* __restrict__ wk,
    const float* __restrict__ wv)
{
    int z = blockIdx.y;
    const float* w = (z == 0) ? wq : (z == 1) ? wk : wv;
    int idx = blockIdx.x * 256 + threadIdx.x;    // = kk*512 + n (coalesced read)
    int kk = idx >> 9, n = idx & 511;
    g_wt16[z][n * DD + kk] = __float2half(w[idx]);
}

// pack 8 consecutive rpr ints into one nibble-packed uint32
__global__ __launch_bounds__(256) void convert_rpr(const int* __restrict__ rpr)
{
    int i = blockIdx.x * 256 + threadIdx.x;      // uint32 output index
    int4 a = ((const int4*)rpr)[2 * i];
    int4 b = ((const int4*)rpr)[2 * i + 1];
    uint32_t o = (uint32_t)(a.x & 15) | ((uint32_t)(a.y & 15) << 4) |
                 ((uint32_t)(a.z & 15) << 8) | ((uint32_t)(a.w & 15) << 12) |
                 ((uint32_t)(b.x & 15) << 16) | ((uint32_t)(b.y & 15) << 20) |
                 ((uint32_t)(b.z & 15) << 24) | ((uint32_t)(b.w & 15) << 28);
    ((uint32_t*)g_rpr4)[i] = o;
}

// ===========================================================================
// Projection via single-plane fp16 mma.sync, cp.async double-buffered
// buffer (27648 B): A 0(18432 = 128x144) ; B 18432(9216 = 64x144)
// ===========================================================================
#define PBUF 27648
#define PROJ_SMEM (2*PBUF)

__global__ __launch_bounds__(256, 3) void proj_mma(
    const float* __restrict__ bq, const float* __restrict__ bk,
    const float* __restrict__ bv)
{
    extern __shared__ __align__(16) char psm[];
    const uint32_t sbase = smem_u32(psm);
    const int tid = threadIdx.x;
    const int wid = tid >> 5, lane = tid & 31;
    const int wm = wid & 3, wn = wid >> 2;
    const int r4 = lane >> 2, kp = lane & 3;
    const int z = blockIdx.z;
    const int n0 = blockIdx.x * 64;
    const int m0 = blockIdx.y * 128;

    const __half* X = g_x16[z];
    const __half* W = g_wt16[z];
    const float* bias = (z == 0) ? bq : (z == 1) ? bk : bv;
    __half* out16 = g_p16[z];

    float acc[2][4][4] = {};

    const uint32_t a_rel = (uint32_t)((wm * 32 + (lane & 15)) * 144 +
                                      ((lane >> 4) << 4));
    const uint32_t b_rel = (uint32_t)(18432 +
        ((wn * 32 + (lane & 7) + ((lane >> 4) << 3)) * 144) +
        (((lane >> 3) & 1) << 4));

    {
        #pragma unroll
        for (int it = 0; it < 4; it++) {
            int u = tid + 256 * it;
            int row = u >> 3, c8 = u & 7;
            CP16(sbase + (uint32_t)(row * 144 + c8 * 16),
                 X + (size_t)(m0 + row) * DD + c8 * 8);
        }
        #pragma unroll
        for (int it = 0; it < 2; it++) {
            int u = tid + 256 * it;
            int row = u >> 3, c8 = u & 7;
            CP16(sbase + (uint32_t)(18432 + row * 144 + c8 * 16),
                 W + (size_t)(n0 + row) * DD + c8 * 8);
        }
        CP_COMMIT();
    }

    for (int ch = 0; ch < 8; ch++) {
        const int cur = ch & 1;
        __syncthreads();
        if (ch < 7) {
            const int k0 = (ch + 1) * 64;
            const uint32_t ob = sbase + (uint32_t)((1 - cur) * PBUF);
            #pragma unroll
            for (int it = 0; it < 4; it++) {
                int u = tid + 256 * it;
                int row = u >> 3, c8 = u & 7;
                CP16(ob + (uint32_t)(row * 144 + c8 * 16),
                     X + (size_t)(m0 + row) * DD + k0 + c8 * 8);
            }
            #pragma unroll
            for (int it = 0; it < 2; it++) {
                int u = tid + 256 * it;
                int row = u >> 3, c8 = u & 7;
                CP16(ob + (uint32_t)(18432 + row * 144 + c8 * 16),
                     W + (size_t)(n0 + row) * DD + k0 + c8 * 8);
            }
            CP_COMMIT();
            CP_WAIT1();
        } else {
            CP_WAIT0();
        }
        __syncthreads();

        const uint32_t ob = sbase + (uint32_t)(cur * PBUF);
        const uint32_t a_b = ob + a_rel;
        const uint32_t b_b = ob + b_rel;

        #pragma unroll
        for (int ks = 0; ks < 4; ks++) {
            const uint32_t ko = (uint32_t)(ks * 32);
            uint32_t af[2][4], bf[4][2];
            #pragma unroll
            for (int mi = 0; mi < 2; mi++)
                ldmatrix_x4(af[mi][0], af[mi][1], af[mi][2], af[mi][3],
                            a_b + (uint32_t)(mi * 16 * 144) + ko);
            #pragma unroll
            for (int nip = 0; nip < 2; nip++) {
                uint32_t r0, r1, r2, r3;
                ldmatrix_x4(r0, r1, r2, r3,
                            b_b + (uint32_t)(nip * 16 * 144) + ko);
                bf[2*nip][0] = r0; bf[2*nip][1] = r1;
                bf[2*nip+1][0] = r2; bf[2*nip+1][1] = r3;
            }
            #pragma unroll
            for (int mi = 0; mi < 2; mi++)
                #pragma unroll
                for (int ni = 0; ni < 4; ni++)
                    mma_f16(acc[mi][ni], af[mi], bf[ni]);
        }
    }

    const int head = n0 >> 6;
    #pragma unroll
    for (int mi = 0; mi < 2; mi++) {
        int m = m0 + wm * 32 + mi * 16 + r4;
        int b_ = m >> 10, s = m & 1023;
        __half* op = out16 + ((((size_t)b_ * HH + head) * SS + s) << 6);
        #pragma unroll
        for (int ni = 0; ni < 4; ni++) {
            int col = wn * 32 + ni * 8 + kp * 2;
            float bx = bias[n0 + col], by = bias[n0 + col + 1];
            *(uint32_t*)(op + col) =
                pack_h2(acc[mi][ni][0] + bx, acc[mi][ni][1] + by);
            *(uint32_t*)(op + (8 << 6) + col) =
                pack_h2(acc[mi][ni][2] + bx, acc[mi][ni][3] + by);
        }
    }
}

// ===========================================================================
// Fused attention v8: nibble rpr, exp2 w/ prescaled qr, l derived from
// bucket sums, lane-private bucket accumulators.
// buffer (22528 B): KH 0(9216) VH 9216(9216) RP4 18432(4096, stride 32)
// ===========================================================================
#define BUFB 22528
#define QR_F (2*BUFB/4)         // 11264
#define KR_F (QR_F + 1536)      // 12800
#define WS_F (KR_F + 704)       // 13504 ; region 128*4*13 = 6656 floats
#define ATT_SMEM ((WS_F + 6656) * 4)   // 80640 B

__global__ __launch_bounds__(256, 2) void attn_tc(
    const float* __restrict__ krpr, float* __restrict__ out)
{
    extern __shared__ __align__(16) float smf[];
    char* Ub = (char*)smf;
    const uint32_t sbase = smem_u32(Ub);
    float* qr   = smf + QR_F;           // 128 x 12, prescaled by EC
    float* krs  = smf + KR_F;
    float* w_sm = smf + WS_F;           // [row][t][13], stride 52 per row
    uint32_t* Qh2 = (uint32_t*)(Ub + BUFB);
    __half*   Qhp = (__half*)(Ub + BUFB);

    const int tid = threadIdx.x;
    const int wm = tid >> 5;
    const int lane = tid & 31;
    const int g = lane >> 2, t = lane & 3;
    const int b = blockIdx.z, h = blockIdx.y;
    const int q0 = blockIdx.x * 128;
    const int bh = b * HH + h;
    const __half* Qg = g_p16[0] + ((size_t)(bh * SS + q0) << 6);
    const __half* Kg = g_p16[1] + ((size_t)(bh * SS) << 6);
    const __half* Vg = g_p16[2] + ((size_t)(bh * SS) << 6);

    // ---- prepass: cp.async Q -> buf1 (group 0), tile0 K/V/rpr -> buf0 ----
    #pragma unroll
    for (int it = 0; it < 4; it++) {
        int u = tid + 256 * it;
        int row = u >> 3, grp = u & 7;
        CP16(sbase + (uint32_t)(BUFB + row * 144 + grp * 16),
             Qg + ((size_t)row << 6) + grp * 8);
    }
    CP_COMMIT();
    {
        #pragma unroll
        for (int it = 0; it < 2; it++) {
            int u = tid + 256 * it;
            int row = u >> 3, grp = u & 7;
            uint32_t d = sbase + (uint32_t)(row * 144 + grp * 16);
            CP16(d,          Kg + ((size_t)row << 6) + grp * 8);
            CP16(d + 9216u,  Vg + ((size_t)row << 6) + grp * 8);
        }
        {
            int row = tid >> 1, half = tid & 1;
            CP16(sbase + (uint32_t)(18432 + row * 32 + half * 16),
                 g_rpr4 + (size_t)(q0 + row) * (SS / 2) + half * 16);
        }
        CP_COMMIT();
    }
    for (int e = tid; e < 704; e += 256) krs[e] = krpr[e];
    for (int e = tid; e < 6656; e += 256) w_sm[e] = 0.f;
    CP_WAIT1();
    __syncthreads();

    // qr[row][r] = (q_row . krpr[r]) * EC   (prescaled for exp2)
    for (int e = tid; e < 128 * NR; e += 256) {
        int row = e / NR, r = e - row * NR;
        float s = 0.f;
        #pragma unroll
        for (int d = 0; d < 64; d++)
            s += __half2float(Qhp[row * 72 + d]) * krs[r * 64 + d];
        qr[row * 12 + r] = s * EC;
    }
    __syncthreads();

    const int row_lo = wm * 16 + g;
    const int row_hi = row_lo + 8;
    float* wl = w_sm + row_lo * 52 + t * 13;
    float* wh = w_sm + row_hi * 52 + t * 13;

    uint32_t qa[4][4];
    #pragma unroll
    for (int ks = 0; ks < 4; ks++) {
        qa[ks][0] = Qh2[row_lo * 36 + 8 * ks + t];
        qa[ks][1] = Qh2[row_hi * 36 + 8 * ks + t];
        qa[ks][2] = Qh2[row_lo * 36 + 8 * ks + t + 4];
        qa[ks][3] = Qh2[row_hi * 36 + 8 * ks + t + 4];
    }

    const uint32_t k_rel = (uint32_t)((((lane & 7) + ((lane >> 4) << 3)) * 144) +
                                      (((lane >> 3) & 1) << 4));
    const uint32_t v_rel = 9216u + (uint32_t)((lane & 15) * 144 +
                                              (lane >> 4) * 16);

    float acc[8][4] = {};

    for (int i = 0; i < 16; i++) {
        const int cur = i & 1;
        __syncthreads();
        if (i < 15) {
            const int kt = (i + 1) * 64;
            const uint32_t ob = sbase + (uint32_t)((1 - cur) * BUFB);
            #pragma unroll
            for (int it = 0; it < 2; it++) {
                int u = tid + 256 * it;
                int row = u >> 3, grp = u & 7;
                uint32_t d = ob + (uint32_t)(row * 144 + grp * 16);
                CP16(d,         Kg + ((size_t)(kt + row) << 6) + grp * 8);
                CP16(d + 9216u, Vg + ((size_t)(kt + row) << 6) + grp * 8);
            }
            {
                int row = tid >> 1, half = tid & 1;
                CP16(ob + (uint32_t)(18432 + row * 32 + half * 16),
                     g_rpr4 + (size_t)(q0 + row) * (SS / 2) + (kt >> 1) +
                     half * 16);
            }
            CP_COMMIT();
            CP_WAIT1();
        } else {
            CP_WAIT0();
        }
        __syncthreads();

        const uint32_t ob = sbase + (uint32_t)(cur * BUFB);
        const uint32_t kb = ob + k_rel;
        const uint32_t vb = ob + v_rel;
        const uint8_t* rp4 = (const uint8_t*)(Ub + cur * BUFB + 18432);

        // ---- GEMM1: S = Q K^T ----
        float s_acc[8][4] = {};
        #pragma unroll
        for (int ks = 0; ks < 4; ks++) {
            #pragma unroll
            for (int ntp = 0; ntp < 4; ntp++) {
                uint32_t r0, r1, r2, r3;
                ldmatrix_x4(r0, r1, r2, r3,
                            kb + (uint32_t)(ntp * 2304 + ks * 32));
                uint32_t b0[2] = {r0, r1}, b1[2] = {r2, r3};
                mma_f16(s_acc[2*ntp],     qa[ks], b0);
                mma_f16(s_acc[2*ntp + 1], qa[ks], b1);
            }
        }

        // ---- RPR bias + exp2 + lane-private bucket accumulation ----
        #pragma unroll
        for (int nt = 0; nt < 8; nt++) {
            uint32_t c01 = rp4[row_lo * 32 + nt * 4 + t];
            uint32_t c23 = rp4[row_hi * 32 + nt * 4 + t];
            int r0 = c01 & 15, r1 = c01 >> 4;
            int r2 = c23 & 15, r3 = c23 >> 4;
            float p0 = exp2f(fmaf(s_acc[nt][0], EC, qr[row_lo * 12 + r0]));
            float p1 = exp2f(fmaf(s_acc[nt][1], EC, qr[row_lo * 12 + r1]));
            float p2 = exp2f(fmaf(s_acc[nt][2], EC, qr[row_hi * 12 + r2]));
            float p3 = exp2f(fmaf(s_acc[nt][3], EC, qr[row_hi * 12 + r3]));
            wl[r0] += p0;
            wl[r1] += p1;
            wh[r2] += p2;
            wh[r3] += p3;
            s_acc[nt][0] = p0; s_acc[nt][1] = p1;
            s_acc[nt][2] = p2; s_acc[nt][3] = p3;
        }

        // ---- GEMM2: acc += P V ----
        #pragma unroll
        for (int ks2 = 0; ks2 < 4; ks2++) {
            uint32_t pa[4];
            pa[0] = pack_h2(s_acc[2*ks2][0],   s_acc[2*ks2][1]);
            pa[1] = pack_h2(s_acc[2*ks2][2],   s_acc[2*ks2][3]);
            pa[2] = pack_h2(s_acc[2*ks2+1][0], s_acc[2*ks2+1][1]);
            pa[3] = pack_h2(s_acc[2*ks2+1][2], s_acc[2*ks2+1][3]);
            #pragma unroll
            for (int np = 0; np < 4; np++) {
                uint32_t r0, r1, r2, r3;
                ldmatrix_x4_t(r0, r1, r2, r3,
                              vb + (uint32_t)(ks2 * 2304 + np * 32));
                uint32_t b0[2] = {r0, r1}, b1[2] = {r2, r3};
                mma_f16(acc[2*np],     pa, b0);
                mma_f16(acc[2*np + 1], pa, b1);
            }
        }
    }

    __syncwarp();   // all lanes' private bucket copies visible within the warp

    // combine the 4 lane-copies per row; l = sum over all buckets
    float wrow_lo[NR], wrow_hi[NR];
    float l_lo = 0.f, l_hi = 0.f;
    #pragma unroll
    for (int r = 0; r < NR; r++) {
        const float* bl = w_sm + row_lo * 52 + r;
        const float* bh2 = w_sm + row_hi * 52 + r;
        wrow_lo[r] = bl[0] + bl[13] + bl[26] + bl[39];
        wrow_hi[r] = bh2[0] + bh2[13] + bh2[26] + bh2[39];
        l_lo += wrow_lo[r];
        l_hi += wrow_hi[r];
    }

    // ---- epilogue: bucket term + normalize, write [B,S,D] ----
    float il_lo = 1.f / l_lo, il_hi = 1.f / l_hi;
    float* outp = out + (size_t)(b * SS + q0) * DD + (h << 6);
    #pragma unroll
    for (int nt = 0; nt < 8; nt++) {
        int col = nt * 8 + 2 * t;
        float e0 = 0.f, e1 = 0.f, e2 = 0.f, e3 = 0.f;
        #pragma unroll
        for (int r = 0; r < NR; r++) {
            float k0 = krs[r * 64 + col], k1 = krs[r * 64 + col + 1];
            e0 += wrow_lo[r] * k0; e1 += wrow_lo[r] * k1;
            e2 += wrow_hi[r] * k0; e3 += wrow_hi[r] * k1;
        }
        float2 o_lo = {(acc[nt][0] + e0) * il_lo, (acc[nt][1] + e1) * il_lo};
        float2 o_hi = {(acc[nt][2] + e2) * il_hi, (acc[nt][3] + e3) * il_hi};
        *(float2*)(outp + (size_t)row_lo * DD + col) = o_lo;
        *(float2*)(outp + (size_t)row_hi * DD + col) = o_hi;
    }
}

// ===========================================================================
extern "C" void kernel_launch(void* const* d_in, const int* in_sizes, int n_in,
                              void* d_out, int out_size)
{
    (void)in_sizes; (void)n_in; (void)out_size;
    const float* q    = (const float*)d_in[0];
    const float* k    = (const float*)d_in[1];
    const float* v    = (const float*)d_in[2];
    const int*   rpr  = (const int*)  d_in[3];
    const float* wq   = (const float*)d_in[4];
    const float* wqb  = (const float*)d_in[5];
    const float* wk   = (const float*)d_in[6];
    const float* wkb  = (const float*)d_in[7];
    const float* wv   = (const float*)d_in[8];
    const float* wvb  = (const float*)d_in[9];
    const float* krpr = (const float*)d_in[10];
    float* out = (float*)d_out;

    cudaFuncSetAttribute(proj_mma,
                         cudaFuncAttributeMaxDynamicSharedMemorySize, PROJ_SMEM);
    cudaFuncSetAttribute(attn_tc,
                         cudaFuncAttributeMaxDynamicSharedMemorySize, ATT_SMEM);

    convert_x<<<dim3((BB*SS*DD/8) / 256, 3), 256>>>(q, k, v);
    convert_w<<<dim3((DD*DD) / 256, 3), 256>>>(wq, wk, wv);
    convert_rpr<<<(SS*SS/8) / 256, 256>>>(rpr);

    proj_mma<<<dim3(DD / 64, (BB * SS) / 128, 3), 256, PROJ_SMEM>>>(wqb, wkb, wvb);

    attn_tc<<<dim3(SS / 128, HH, BB), 256, ATT_SMEM>>>(krpr, out);
}